// round 3
// baseline (speedup 1.0000x reference)
#include <cuda_runtime.h>

#define N_SAMPLES   2048
#define N_CHAN      512
#define HW          49
#define N_GROUPS    64
#define CH_PER_CTA  128
#define CHUNKS      (N_CHAN / CH_PER_CTA)          // 4
#define THREADS     128
#define F4_PER_CTA  (CH_PER_CTA * HW / 4)          // 1568
#define GRID        (N_SAMPLES * CHUNKS)           // 8192
#define OUT_ELEMS   (N_GROUPS * N_CHAN)            // 32768

// Scratch (device globals: zero at module load; the fused tail resets them
// after every use so each graph replay starts clean).
__device__ float    g_acc[OUT_ELEMS];
__device__ int      g_cnt[N_GROUPS];
__device__ unsigned g_done = 0;

__global__ __launch_bounds__(THREADS) void accum_kernel(
    const float* __restrict__ x,
    const int*   __restrict__ idx,
    float*       __restrict__ out)
{
    __shared__ float s[CH_PER_CTA * HW];           // 25088 B
    __shared__ float s_recip[N_GROUPS];
    __shared__ int   s_last;

    const int b     = blockIdx.x;
    const int n     = b >> 2;                      // sample
    const int chunk = b & 3;                       // 128-channel chunk
    const int tid   = threadIdx.x;
    const int g     = __ldg(&idx[n]);

    if (chunk == 0 && tid == 0) atomicAdd(&g_cnt[g], 1);

    // ---- Phase 1: stage chunk into smem, fully coalesced float4 ----
    const float4* __restrict__ src =
        (const float4*)(x + ((size_t)n * N_CHAN + chunk * CH_PER_CTA) * HW);
    float4* s4 = (float4*)s;
    #pragma unroll
    for (int i = 0; i < 13; i++) {
        int j = tid + i * THREADS;
        if (j < F4_PER_CTA) s4[j] = src[j];
    }
    __syncthreads();

    // ---- Phase 2: each thread sums its channel (stride 49 words: odd =>
    // bank-conflict-free), one scalar atomic per channel ----
    const float* __restrict__ row = s + tid * HW;
    float sum = 0.0f;
    #pragma unroll
    for (int e = 0; e < HW; e++) sum += row[e];
    atomicAdd(&g_acc[g * N_CHAN + chunk * CH_PER_CTA + tid], sum);

    // ---- Completion ticket: last CTA finalizes + resets scratch ----
    __threadfence();
    __syncthreads();
    if (tid == 0) {
        unsigned t = atomicAdd(&g_done, 1u);
        s_last = (t == (unsigned)(GRID - 1));
    }
    __syncthreads();
    if (!s_last) return;

    __threadfence();   // acquire: all CTAs' atomics now visible

    // reciprocal table (avoids a division per output element)
    if (tid < N_GROUPS) {
        int c = g_cnt[tid];
        s_recip[tid] = 1.0f / ((float)c * (float)HW);
        g_cnt[tid] = 0;                            // reset for next replay
    }
    __syncthreads();

    float4* acc4 = (float4*)g_acc;
    float4* out4 = (float4*)out;
    const float4 zero4 = make_float4(0.0f, 0.0f, 0.0f, 0.0f);
    #pragma unroll 4
    for (int i4 = tid; i4 < OUT_ELEMS / 4; i4 += THREADS) {
        int   gg = i4 >> 7;                        // 128 float4 per group row
        float r  = s_recip[gg];
        float4 v = acc4[i4];
        out4[i4] = make_float4(v.x * r, v.y * r, v.z * r, v.w * r);
        acc4[i4] = zero4;                          // reset for next replay
    }
    if (tid == 0) g_done = 0;
}

extern "C" void kernel_launch(void* const* d_in, const int* in_sizes, int n_in,
                              void* d_out, int out_size)
{
    const float* x   = (const float*)d_in[0];
    const int*   idx = (const int*)d_in[1];
    float*       out = (float*)d_out;

    (void)in_sizes; (void)n_in; (void)out_size;

    accum_kernel<<<GRID, THREADS>>>(x, idx, out);
}

// round 4
// speedup vs baseline: 1.4003x; 1.4003x over previous
#include <cuda_runtime.h>
#include <cstdint>

#define N_SAMPLES   2048
#define N_CHAN      512
#define HW          49
#define N_GROUPS    64
#define THREADS     256
#define WARPS       8
#define OUT_ELEMS   (N_GROUPS * N_CHAN)        // 32768

// Per-group reciprocal of (count * 49), recomputed every replay by prep_kernel.
__device__ float g_recip[N_GROUPS];

__device__ __forceinline__ uint32_t smem_u32(const void* p) {
    return (uint32_t)__cvta_generic_to_shared(p);
}
__device__ __forceinline__ void cp_async16(uint32_t s, const void* g) {
    asm volatile("cp.async.cg.shared.global [%0], [%1], 16;\n" :: "r"(s), "l"(g));
}

// ---------------------------------------------------------------------------
// Kernel 0: CTA c zeroes its slice of out and computes g_recip[c].
// ---------------------------------------------------------------------------
__global__ __launch_bounds__(THREADS) void prep_kernel(
    const int* __restrict__ idx, float* __restrict__ out)
{
    const int c   = blockIdx.x;               // group id, 0..63
    const int tid = threadIdx.x;

    // zero this group's 512 output floats (128 float4)
    float4* o4 = (float4*)(out + c * N_CHAN);
    if (tid < N_CHAN / 4) o4[tid] = make_float4(0.f, 0.f, 0.f, 0.f);

    // count members of group c
    __shared__ int s_total;
    if (tid == 0) s_total = 0;
    __syncthreads();

    int cnt = 0;
    for (int i = tid; i < N_SAMPLES; i += THREADS) cnt += (idx[i] == c);
    cnt += __shfl_down_sync(0xFFFFFFFFu, cnt, 16);
    cnt += __shfl_down_sync(0xFFFFFFFFu, cnt, 8);
    cnt += __shfl_down_sync(0xFFFFFFFFu, cnt, 4);
    cnt += __shfl_down_sync(0xFFFFFFFFu, cnt, 2);
    cnt += __shfl_down_sync(0xFFFFFFFFu, cnt, 1);
    if ((tid & 31) == 0) atomicAdd(&s_total, cnt);
    __syncthreads();

    if (tid == 0) g_recip[c] = 1.0f / ((float)s_total * (float)HW);
}

// ---------------------------------------------------------------------------
// Kernel 1: one CTA per sample. Warp w owns channels [64w, 64w+64).
// Per outer iteration a warp cp.asyncs four 4-channel blocks (196 floats each,
// 16B-aligned) into warp-private smem, then 8 lanes per channel do a stride-8
// serial sum + 3 width-8 shuffles. Pre-scaled atomicAdd straight into out.
// ---------------------------------------------------------------------------
__global__ __launch_bounds__(THREADS, 8) void accum_kernel(
    const float* __restrict__ x,
    const int*   __restrict__ idx,
    float*       __restrict__ out)
{
    // [warp][block][50 float4]  (49 used, +1 pad to shift banks per block)
    __shared__ float4 sbuf[WARPS][4][50];

    const int n    = blockIdx.x;
    const int g    = __ldg(&idx[n]);
    const int w    = threadIdx.x >> 5;
    const int lane = threadIdx.x & 31;
    const int sw   = lane >> 3;               // subwarp 0..3 -> channel in block
    const int r    = lane & 7;                // rank within subwarp

    const float  recip = __ldg(&g_recip[g]);
    const float4* __restrict__ src4 =
        (const float4*)(x + (size_t)n * (N_CHAN * HW));
    float* __restrict__ out_g = out + g * N_CHAN;

    #pragma unroll
    for (int o = 0; o < 4; o++) {
        // ---- stage 4 blocks (16 channels) via cp.async, front-batched ----
        #pragma unroll
        for (int b = 0; b < 4; b++) {
            const float4* p = src4 + (16 * w + 4 * o + b) * HW;  // 49 f4/block
            cp_async16(smem_u32(&sbuf[w][b][lane]), p + lane);
            if (lane < HW - 32)
                cp_async16(smem_u32(&sbuf[w][b][32 + lane]), p + 32 + lane);
        }
        asm volatile("cp.async.commit_group;\n" ::: "memory");
        asm volatile("cp.async.wait_group 0;\n" ::: "memory");
        __syncwarp();

        // ---- reduce: 8 lanes per channel, stride-8, then 3 shuffles ----
        #pragma unroll
        for (int b = 0; b < 4; b++) {
            const float* cbase = (const float*)&sbuf[w][b][0] + HW * sw;
            float s = 0.0f;
            #pragma unroll
            for (int k = 0; k < 7; k++) {
                int e = r + 8 * k;
                if (e < HW) s += cbase[e];
            }
            s += __shfl_down_sync(0xFFFFFFFFu, s, 4, 8);
            s += __shfl_down_sync(0xFFFFFFFFu, s, 2, 8);
            s += __shfl_down_sync(0xFFFFFFFFu, s, 1, 8);
            if (r == 0)
                atomicAdd(&out_g[64 * w + 16 * o + 4 * b + sw], s * recip);
        }
        __syncwarp();   // reads done before next iteration's cp.async overwrite
    }
}

extern "C" void kernel_launch(void* const* d_in, const int* in_sizes, int n_in,
                              void* d_out, int out_size)
{
    const float* x   = (const float*)d_in[0];
    const int*   idx = (const int*)d_in[1];
    float*       out = (float*)d_out;

    (void)in_sizes; (void)n_in; (void)out_size;

    prep_kernel<<<N_GROUPS, THREADS>>>(idx, out);
    accum_kernel<<<N_SAMPLES, THREADS>>>(x, idx, out);
}

// round 6
// speedup vs baseline: 1.4014x; 1.0008x over previous
#include <cuda_runtime.h>
#include <cstdint>

#define N_SAMPLES 2048
#define N_CHAN    512
#define HW        49
#define N_GROUPS  64
#define CHB       8                       // channels per CTA
#define QCH       (N_CHAN / CHB)          // 64 channel-chunks
#define GRID      (N_GROUPS * QCH)        // 4096
#define THREADS   128
#define STRIP_F4  98                      // CHB*HW/4 float4 per member strip
#define SAMPLE_F4 (N_CHAN * HW / 4)       // 6272 float4 per sample
#define NBUF      4

__device__ __forceinline__ uint32_t smem_u32(const void* p) {
    return (uint32_t)__cvta_generic_to_shared(p);
}
__device__ __forceinline__ void cp_async16(uint32_t s, const void* g) {
    asm volatile("cp.async.cg.shared.global [%0], [%1], 16;\n"
                 :: "r"(s), "l"(g) : "memory");
}
__device__ __forceinline__ void cp_commit() {
    asm volatile("cp.async.commit_group;\n" ::: "memory");
}
__device__ __forceinline__ void cp_wait3() {
    asm volatile("cp.async.wait_group 3;\n" ::: "memory");
}
__device__ __forceinline__ void cp_wait0() {
    asm volatile("cp.async.wait_group 0;\n" ::: "memory");
}

// One CTA per (group, 8-channel chunk). Scans idx for its members, streams
// each member's contiguous 1568-byte strip through a 4-slot cp.async ring,
// accumulates float4 partials in registers, writes 8 outputs with plain STG.
// No global atomics, no scratch, no zero-init, single launch.
__global__ __launch_bounds__(THREADS) void fused_kernel(
    const float* __restrict__ x,
    const int*   __restrict__ idx,
    float*       __restrict__ out)
{
    __shared__ float4         buf[NBUF][STRIP_F4];   // 6272 B
    __shared__ unsigned short list[N_SAMPLES];       // 4096 B (sample ids < 2048)
    __shared__ int            s_cnt;
    __shared__ float4         red4[STRIP_F4];        // 392 partials, 16B-aligned

    const int g   = blockIdx.x & (N_GROUPS - 1);
    const int q   = blockIdx.x >> 6;
    const int tid = threadIdx.x;

    if (tid == 0) s_cnt = 0;
    __syncthreads();

    // ---- scan idx, compact members of group g (order-free compaction) ----
    const int4* __restrict__ idx4 = (const int4*)idx;
    for (int i = tid; i < N_SAMPLES / 4; i += THREADS) {
        int4 v = idx4[i];
        int  b = 4 * i;
        if (v.x == g) list[atomicAdd(&s_cnt, 1)] = (unsigned short)(b + 0);
        if (v.y == g) list[atomicAdd(&s_cnt, 1)] = (unsigned short)(b + 1);
        if (v.z == g) list[atomicAdd(&s_cnt, 1)] = (unsigned short)(b + 2);
        if (v.w == g) list[atomicAdd(&s_cnt, 1)] = (unsigned short)(b + 3);
    }
    __syncthreads();
    const int cnt = s_cnt;

    // ---- pipelined streaming: member i lives in commit-group i, slot i&3 ----
    const float4* __restrict__ xq = (const float4*)x + (size_t)q * STRIP_F4;

    // prologue: members 0..2 (empty commit groups if cnt small — harmless)
    #pragma unroll
    for (int p = 0; p < NBUF - 1; p++) {
        if (p < cnt && tid < STRIP_F4)
            cp_async16(smem_u32(&buf[p][tid]),
                       xq + (size_t)list[p] * SAMPLE_F4 + tid);
        cp_commit();
    }

    float4 acc = make_float4(0.f, 0.f, 0.f, 0.f);
    for (int i = 0; i < cnt; i++) {
        int j = i + NBUF - 1;                        // member staged this iter
        if (j < cnt && tid < STRIP_F4)
            cp_async16(smem_u32(&buf[j & (NBUF - 1)][tid]),
                       xq + (size_t)list[j] * SAMPLE_F4 + tid);
        cp_commit();
        cp_wait3();                                  // member i's group done
        if (tid < STRIP_F4) {
            float4 v = buf[i & (NBUF - 1)][tid];
            acc.x += v.x; acc.y += v.y; acc.z += v.z; acc.w += v.w;
        }
        __syncthreads();   // reads of slot i&3 done before its reuse at i+1
    }
    cp_wait0();

    // ---- final: 392 partials -> 8 channel sums -> scaled STG ----
    if (tid < STRIP_F4) red4[tid] = acc;
    __syncthreads();

    if (tid < CHB) {
        const float* __restrict__ r = (const float*)red4 + tid * HW;
        float s = 0.f;
        #pragma unroll
        for (int e = 0; e < HW; e++) s += r[e];
        float rcp = 1.0f / ((float)cnt * (float)HW);
        out[g * N_CHAN + q * CHB + tid] = s * rcp;
    }
}

extern "C" void kernel_launch(void* const* d_in, const int* in_sizes, int n_in,
                              void* d_out, int out_size)
{
    const float* x   = (const float*)d_in[0];
    const int*   idx = (const int*)d_in[1];
    float*       out = (float*)d_out;

    (void)in_sizes; (void)n_in; (void)out_size;

    fused_kernel<<<GRID, THREADS>>>(x, idx, out);
}

// round 7
// speedup vs baseline: 1.4821x; 1.0576x over previous
#include <cuda_runtime.h>
#include <cstdint>

#define N_SAMPLES 2048
#define N_CHAN    512
#define HW        49
#define N_GROUPS  64
#define CHB       8                       // channels per CTA
#define QCH       (N_CHAN / CHB)          // 64 channel-chunks
#define GRID      (N_GROUPS * QCH)        // 4096
#define THREADS   128
#define STRIP_F4  98                      // CHB*HW/4 float4 per member strip
#define SAMPLE_F4 (N_CHAN * HW / 4)       // 6272 float4 per sample
#define NBUF      8                       // pipeline depth (7 in flight)

__device__ __forceinline__ uint32_t smem_u32(const void* p) {
    return (uint32_t)__cvta_generic_to_shared(p);
}
__device__ __forceinline__ void cp_async16(uint32_t s, const void* g) {
    asm volatile("cp.async.cg.shared.global [%0], [%1], 16;\n"
                 :: "r"(s), "l"(g) : "memory");
}
__device__ __forceinline__ void cp_commit() {
    asm volatile("cp.async.commit_group;\n" ::: "memory");
}
__device__ __forceinline__ void cp_wait7() {
    asm volatile("cp.async.wait_group 7;\n" ::: "memory");
}
__device__ __forceinline__ void cp_wait0() {
    asm volatile("cp.async.wait_group 0;\n" ::: "memory");
}

// One CTA per (group, 8-channel chunk). Scans idx for its members, then
// streams each member's contiguous 1568-byte strip through an 8-slot
// cp.async ring. Slots are THREAD-PRIVATE (thread tid writes and reads only
// buf[slot][tid]), so the member loop needs NO barriers: wait_group alone
// orders a thread's own copies. No global atomics, no scratch, one launch.
__global__ __launch_bounds__(THREADS) void fused_kernel(
    const float* __restrict__ x,
    const int*   __restrict__ idx,
    float*       __restrict__ out)
{
    __shared__ float4         buf[NBUF][STRIP_F4];   // 12544 B
    __shared__ unsigned short list[N_SAMPLES];       // 4096 B
    __shared__ int            s_cnt;
    __shared__ float4         red4[STRIP_F4];        // 1568 B, 16B-aligned

    const int g   = blockIdx.x & (N_GROUPS - 1);
    const int q   = blockIdx.x >> 6;
    const int tid = threadIdx.x;

    if (tid == 0) s_cnt = 0;
    __syncthreads();

    // ---- scan idx, compact members of group g (order-free compaction) ----
    const int4* __restrict__ idx4 = (const int4*)idx;
    for (int i = tid; i < N_SAMPLES / 4; i += THREADS) {
        int4 v = idx4[i];
        int  b = 4 * i;
        if (v.x == g) list[atomicAdd(&s_cnt, 1)] = (unsigned short)(b + 0);
        if (v.y == g) list[atomicAdd(&s_cnt, 1)] = (unsigned short)(b + 1);
        if (v.z == g) list[atomicAdd(&s_cnt, 1)] = (unsigned short)(b + 2);
        if (v.w == g) list[atomicAdd(&s_cnt, 1)] = (unsigned short)(b + 3);
    }
    __syncthreads();
    const int cnt = s_cnt;

    const float4* __restrict__ xq = (const float4*)x + (size_t)q * STRIP_F4;
    const bool active = (tid < STRIP_F4);

    // ---- prologue: stage members 0..NBUF-2 (empty groups if cnt small) ----
    #pragma unroll
    for (int p = 0; p < NBUF - 1; p++) {
        if (p < cnt && active)
            cp_async16(smem_u32(&buf[p][tid]),
                       xq + (size_t)list[p] * SAMPLE_F4 + tid);
        cp_commit();
    }

    // ---- barrier-free steady state: 7 strips in flight per CTA ----
    float4 acc = make_float4(0.f, 0.f, 0.f, 0.f);
    for (int i = 0; i < cnt; i++) {
        int j = i + NBUF - 1;
        if (j < cnt && active)
            cp_async16(smem_u32(&buf[j & (NBUF - 1)][tid]),
                       xq + (size_t)list[j] * SAMPLE_F4 + tid);
        cp_commit();
        cp_wait7();                       // this thread's group i complete
        if (active) {
            float4 v = buf[i & (NBUF - 1)][tid];
            acc.x += v.x; acc.y += v.y; acc.z += v.z; acc.w += v.w;
        }
    }
    cp_wait0();

    // ---- final: 392 partials -> 8 channel sums -> scaled STG ----
    if (active) red4[tid] = acc;
    __syncthreads();

    if (tid < CHB) {
        const float* __restrict__ r = (const float*)red4 + tid * HW;
        float s = 0.f;
        #pragma unroll
        for (int e = 0; e < HW; e++) s += r[e];
        float rcp = 1.0f / ((float)cnt * (float)HW);
        out[g * N_CHAN + q * CHB + tid] = s * rcp;
    }
}

extern "C" void kernel_launch(void* const* d_in, const int* in_sizes, int n_in,
                              void* d_out, int out_size)
{
    const float* x   = (const float*)d_in[0];
    const int*   idx = (const int*)d_in[1];
    float*       out = (float*)d_out;

    (void)in_sizes; (void)n_in; (void)out_size;

    fused_kernel<<<GRID, THREADS>>>(x, idx, out);
}

// round 8
// speedup vs baseline: 1.4833x; 1.0008x over previous
#include <cuda_runtime.h>
#include <cstdint>

#define N_SAMPLES 2048
#define N_CHAN    512
#define HW        49
#define N_GROUPS  64
#define CHB       8                       // channels per CTA
#define GRID      (N_GROUPS * (N_CHAN / CHB))   // 4096
#define THREADS   128
#define STRIP_F4  98                      // CHB*HW/4 float4 per member strip
#define SAMPLE_F4 (N_CHAN * HW / 4)       // 6272 float4 per sample

// One CTA per (group, 8-channel chunk). Scans idx for its members, then
// accumulates each member's contiguous 1568-byte strip directly via LDG.128
// into a register float4 (member loop unrolled x4 for MLP). No cp.async, no
// smem staging, no global atomics, no scratch, single launch; every output
// element is written exactly once.
__global__ __launch_bounds__(THREADS) void fused_kernel(
    const float* __restrict__ x,
    const int*   __restrict__ idx,
    float*       __restrict__ out)
{
    __shared__ unsigned short list[N_SAMPLES];   // 4096 B (sample ids < 2048)
    __shared__ int            s_cnt;
    __shared__ float4         red4[STRIP_F4];    // 1568 B, 16B-aligned

    const int g   = blockIdx.x & (N_GROUPS - 1);
    const int q   = blockIdx.x >> 6;
    const int tid = threadIdx.x;

    if (tid == 0) s_cnt = 0;
    __syncthreads();

    // ---- scan idx, compact members of group g (order-free compaction) ----
    const int4* __restrict__ idx4 = (const int4*)idx;
    for (int i = tid; i < N_SAMPLES / 4; i += THREADS) {
        int4 v = idx4[i];
        int  b = 4 * i;
        if (v.x == g) list[atomicAdd(&s_cnt, 1)] = (unsigned short)(b + 0);
        if (v.y == g) list[atomicAdd(&s_cnt, 1)] = (unsigned short)(b + 1);
        if (v.z == g) list[atomicAdd(&s_cnt, 1)] = (unsigned short)(b + 2);
        if (v.w == g) list[atomicAdd(&s_cnt, 1)] = (unsigned short)(b + 3);
    }
    __syncthreads();
    const int cnt = s_cnt;

    const float4* __restrict__ xq = (const float4*)x + (size_t)q * STRIP_F4;
    const bool active = (tid < STRIP_F4);

    // ---- register-accumulating stream, unrolled x4 for MLP ----
    float4 acc = make_float4(0.f, 0.f, 0.f, 0.f);
    int i = 0;
    if (active) {
        for (; i + 4 <= cnt; i += 4) {
            const size_t o0 = (size_t)list[i + 0] * SAMPLE_F4;
            const size_t o1 = (size_t)list[i + 1] * SAMPLE_F4;
            const size_t o2 = (size_t)list[i + 2] * SAMPLE_F4;
            const size_t o3 = (size_t)list[i + 3] * SAMPLE_F4;
            float4 v0 = __ldg(xq + o0 + tid);    // 4 independent LDG.128,
            float4 v1 = __ldg(xq + o1 + tid);    // front-batched
            float4 v2 = __ldg(xq + o2 + tid);
            float4 v3 = __ldg(xq + o3 + tid);
            acc.x += v0.x + v1.x + v2.x + v3.x;
            acc.y += v0.y + v1.y + v2.y + v3.y;
            acc.z += v0.z + v1.z + v2.z + v3.z;
            acc.w += v0.w + v1.w + v2.w + v3.w;
        }
        for (; i < cnt; i++) {
            float4 v = __ldg(xq + (size_t)list[i] * SAMPLE_F4 + tid);
            acc.x += v.x; acc.y += v.y; acc.z += v.z; acc.w += v.w;
        }
        red4[tid] = acc;
    }
    __syncthreads();

    // ---- final: 392 partials -> 8 channel sums -> scaled STG ----
    if (tid < CHB) {
        const float* __restrict__ r = (const float*)red4 + tid * HW;
        float s = 0.f;
        #pragma unroll
        for (int e = 0; e < HW; e++) s += r[e];
        float rcp = 1.0f / ((float)cnt * (float)HW);
        out[g * N_CHAN + q * CHB + tid] = s * rcp;
    }
}

extern "C" void kernel_launch(void* const* d_in, const int* in_sizes, int n_in,
                              void* d_out, int out_size)
{
    const float* x   = (const float*)d_in[0];
    const int*   idx = (const int*)d_in[1];
    float*       out = (float*)d_out;

    (void)in_sizes; (void)n_in; (void)out_size;

    fused_kernel<<<GRID, THREADS>>>(x, idx, out);
}